// round 12
// baseline (speedup 1.0000x reference)
#include <cuda_runtime.h>
#include <cuda_bf16.h>
#include <cuda_fp16.h>
#include <cstdint>

#define BATCH 8
#define SQ    2048
#define SK    2048
#define DIM   256
#define MQ    (BATCH*SQ)

// ---------------- scratch (device globals; no runtime allocation) ----------
__device__ float g_scores[(size_t)BATCH * SQ * SK];
__device__ float g_beff[DIM];

__device__ __nv_bfloat16 g_xh[MQ * DIM],  g_xl[MQ * DIM];
__device__ __nv_bfloat16 g_sh[MQ * DIM],  g_sl[MQ * DIM];
__device__ __nv_bfloat16 g_Wqh[DIM * DIM], g_Wql[DIM * DIM];
__device__ __nv_bfloat16 g_Weh[DIM * DIM], g_Wel[DIM * DIM];
__device__ __nv_bfloat16 g_Wvh[DIM * DIM], g_Wvl[DIM * DIM];
__device__ __nv_bfloat16 g_qh[MQ * DIM],  g_ql[MQ * DIM];
__device__ __nv_bfloat16 g_wkh[MQ * DIM], g_wkl[MQ * DIM];
__device__ __half g_vT[BATCH * DIM * SK];
__device__ __half g_P[(size_t)BATCH * SQ * SK];

// ---------------- helpers ----------------
__device__ __forceinline__ uint32_t smem_u32(const void* p) {
    uint32_t a;
    asm("{ .reg .u64 t; cvta.to.shared.u64 t, %1; cvt.u32.u64 %0, t; }"
        : "=r"(a) : "l"(p));
    return a;
}

// bf16 hi/lo pair packer
__device__ __forceinline__ void splitpair_bf(float a, float b, uint32_t& h, uint32_t& l) {
    __nv_bfloat16 ha = __float2bfloat16(a), hb = __float2bfloat16(b);
    float la = a - __bfloat162float(ha);
    float lb = b - __bfloat162float(hb);
    h = (uint32_t)__bfloat16_as_ushort(ha) | ((uint32_t)__bfloat16_as_ushort(hb) << 16);
    l = (uint32_t)__bfloat16_as_ushort(__float2bfloat16(la)) |
        ((uint32_t)__bfloat16_as_ushort(__float2bfloat16(lb)) << 16);
}

#define CP_ASYNC16(dst, src) \
    asm volatile("cp.async.cg.shared.global [%0], [%1], 16;" \
                 :: "r"(dst), "l"(src) : "memory")
#define CP_COMMIT() asm volatile("cp.async.commit_group;" ::: "memory")
#define CP_WAIT1()  asm volatile("cp.async.wait_group 1;" ::: "memory")
#define CP_WAIT0()  asm volatile("cp.async.wait_group 0;" ::: "memory")

#define LDMATRIX_X4(r0, r1, r2, r3, addr)                                     \
    asm volatile("ldmatrix.sync.aligned.m8n8.x4.shared.b16 {%0,%1,%2,%3}, [%4];" \
                 : "=r"(r0), "=r"(r1), "=r"(r2), "=r"(r3) : "r"(addr))

#define MMA_BF16(c, a, b0, b1)                                                \
    asm volatile("mma.sync.aligned.m16n8k16.row.col.f32.bf16.bf16.f32 "       \
                 "{%0,%1,%2,%3}, {%4,%5,%6,%7}, {%8,%9}, {%0,%1,%2,%3};"      \
                 : "+f"((c)[0]), "+f"((c)[1]), "+f"((c)[2]), "+f"((c)[3])     \
                 : "r"((a)[0]), "r"((a)[1]), "r"((a)[2]), "r"((a)[3]),        \
                   "r"(b0), "r"(b1))

#define MMA_F16(c, a, b0, b1)                                                 \
    asm volatile("mma.sync.aligned.m16n8k16.row.col.f32.f16.f16.f32 "         \
                 "{%0,%1,%2,%3}, {%4,%5,%6,%7}, {%8,%9}, {%0,%1,%2,%3};"      \
                 : "+f"((c)[0]), "+f"((c)[1]), "+f"((c)[2]), "+f"((c)[3])     \
                 : "r"((a)[0]), "r"((a)[1]), "r"((a)[2]), "r"((a)[3]),        \
                   "r"(b0), "r"(b1))

// 2 stages; each stage = up to 3 slots of 16KB (linears/ctx bodies)
#define STAGE_BYTES 49152
#define SMEM_BYTES  98304

// ================= bf16-split GEMM body (R9: single-bar, unrolled) ========
// Used for LINEARS only (K=256 -> T=8, regs stay under 128).
// C = Ah*Bh^T + Ah*Bl^T + Al*Bh^T   (+bias)
// biasMode: 1 per-col, 2 per-row.
// SPLIT: 1 -> bf16 hi/lo (Ch/Cl); 3 -> single fp16 (Ch only).
template <int SPLIT, int K>
__device__ __forceinline__ void gemm_body(
    const __nv_bfloat16* __restrict__ Ah, const __nv_bfloat16* __restrict__ Al,
    const __nv_bfloat16* __restrict__ Bh, const __nv_bfloat16* __restrict__ Bl,
    float* __restrict__ Cf, uint16_t* __restrict__ Ch,
    uint16_t* __restrict__ Cl, const float* __restrict__ bias,
    int biasMode, int lda, int ldb, int ldc, int row0, int col0)
{
    extern __shared__ __align__(128) char smem[];
    const uint32_t sb = smem_u32(smem);
    const int tid = threadIdx.x, lane = tid & 31, wid = tid >> 5;

    constexpr int KT = K >> 6;
    constexpr int T  = 2 * KT;
    const size_t ldaby = (size_t)lda * 2;
    const size_t ldbby = (size_t)ldb * 2;

    auto load_one = [&](const char* g, size_t ldby, uint32_t dst) {
#pragma unroll
        for (int i = 0; i < 4; i++) {
            const int idx = i * 256 + tid;
            const int r = idx >> 3, c = (idx & 7) * 16;
            const uint32_t so = (uint32_t)(r * 128 + (c ^ ((r & 7) << 4)));
            CP_ASYNC16(dst + so, g + (size_t)r * ldby + c);
        }
    };

    auto load_chunk = [&](int t, int p) {
        const uint32_t base = sb + p * STAGE_BYTES;
        if (t < KT) {
            const int kt = t;
            load_one((const char*)(Ah + (size_t)row0 * lda + kt * 64), ldaby, base);
            load_one((const char*)(Bh + (size_t)col0 * ldb + kt * 64), ldbby, base + 16384);
            load_one((const char*)(Bl + (size_t)col0 * ldb + kt * 64), ldbby, base + 32768);
        } else {
            const int kt = t - KT;
            load_one((const char*)(Al + (size_t)row0 * lda + kt * 64), ldaby, base);
            load_one((const char*)(Bh + (size_t)col0 * ldb + kt * 64), ldbby, base + 16384);
        }
        CP_COMMIT();
    };

    float acc[4][4][4];
#pragma unroll
    for (int i = 0; i < 4; i++)
#pragma unroll
        for (int j = 0; j < 4; j++)
#pragma unroll
            for (int e = 0; e < 4; e++) acc[i][j][e] = 0.f;

    // warp layout: 2 (m) x 4 (n); warp tile 64m x 32n
    const int wm0 = (wid & 1) * 64;
    const int wn0 = (wid >> 1) * 32;
    const uint32_t xr = (uint32_t)((lane & 7) << 4);
    const uint32_t aRow = (uint32_t)((wm0 + (lane & 15)) * 128);
    const uint32_t aK0  = (uint32_t)(((lane >> 4) & 1) * 16);
    const uint32_t bRow = (uint32_t)((wn0 + (((lane >> 3) & 2) << 2) + (lane & 7)) * 128);
    const uint32_t bK0  = (uint32_t)(((lane >> 3) & 1) * 16);

    auto compute1 = [&](int p) {
        const uint32_t smA  = sb + p * STAGE_BYTES;
        const uint32_t smBh = smA + 16384;
        const uint32_t smBl = smA + 32768;
#pragma unroll
        for (int ks = 0; ks < 4; ks++) {
            uint32_t a[4][4], bh[2][4], bl[2][4];
#pragma unroll
            for (int mt = 0; mt < 4; mt++) {
                const uint32_t ad = smA + aRow + mt * 2048 + ((aK0 + ks * 32) ^ xr);
                LDMATRIX_X4(a[mt][0], a[mt][1], a[mt][2], a[mt][3], ad);
            }
#pragma unroll
            for (int np = 0; np < 2; np++) {
                const uint32_t off = bRow + np * 2048 + ((bK0 + ks * 32) ^ xr);
                LDMATRIX_X4(bh[np][0], bh[np][1], bh[np][2], bh[np][3], smBh + off);
                LDMATRIX_X4(bl[np][0], bl[np][1], bl[np][2], bl[np][3], smBl + off);
            }
#pragma unroll
            for (int mt = 0; mt < 4; mt++)
#pragma unroll
                for (int nt = 0; nt < 4; nt++) {
                    MMA_BF16(acc[mt][nt], a[mt],
                             bh[nt >> 1][(nt & 1) * 2], bh[nt >> 1][(nt & 1) * 2 + 1]);
                    MMA_BF16(acc[mt][nt], a[mt],
                             bl[nt >> 1][(nt & 1) * 2], bl[nt >> 1][(nt & 1) * 2 + 1]);
                }
        }
    };

    auto compute2 = [&](int p) {
        const uint32_t smA  = sb + p * STAGE_BYTES;
        const uint32_t smBh = smA + 16384;
#pragma unroll
        for (int ks = 0; ks < 4; ks++) {
            uint32_t a[4][4], b[2][4];
#pragma unroll
            for (int mt = 0; mt < 4; mt++) {
                const uint32_t ad = smA + aRow + mt * 2048 + ((aK0 + ks * 32) ^ xr);
                LDMATRIX_X4(a[mt][0], a[mt][1], a[mt][2], a[mt][3], ad);
            }
#pragma unroll
            for (int np = 0; np < 2; np++) {
                const uint32_t bd = smBh + bRow + np * 2048 + ((bK0 + ks * 32) ^ xr);
                LDMATRIX_X4(b[np][0], b[np][1], b[np][2], b[np][3], bd);
            }
#pragma unroll
            for (int mt = 0; mt < 4; mt++)
#pragma unroll
                for (int nt = 0; nt < 4; nt++)
                    MMA_BF16(acc[mt][nt], a[mt],
                             b[nt >> 1][(nt & 1) * 2], b[nt >> 1][(nt & 1) * 2 + 1]);
        }
    };

    // ---- single-bar pipeline: wait(t) -> bar -> load(t+1) -> compute(t) ----
    load_chunk(0, 0);
#pragma unroll
    for (int t = 0; t < T; t++) {
        const int p = t & 1;
        CP_WAIT0();
        __syncthreads();
        if (t + 1 < T) load_chunk(t + 1, p ^ 1);
        if (t < KT) compute1(p); else compute2(p);
    }

    // ---------------- epilogue ----------------
    const int bm = row0 + wm0 + (lane >> 2);
    const int bn = col0 + wn0 + (lane & 3) * 2;
#pragma unroll
    for (int mt = 0; mt < 4; mt++) {
#pragma unroll
        for (int nt = 0; nt < 4; nt++) {
            const int m = bm + mt * 16, n = bn + nt * 8;
            float c0 = acc[mt][nt][0], c1 = acc[mt][nt][1];
            float c2 = acc[mt][nt][2], c3 = acc[mt][nt][3];
            if (biasMode == 1) {
                const float b0v = bias[n], b1v = bias[n + 1];
                c0 += b0v; c1 += b1v; c2 += b0v; c3 += b1v;
            } else if (biasMode == 2) {
                c0 += bias[m]; c1 += bias[m];
                c2 += bias[m + 8]; c3 += bias[m + 8];
            }
            if (SPLIT == 1) {
                uint32_t h0, l0, h1, l1;
                splitpair_bf(c0, c1, h0, l0);
                splitpair_bf(c2, c3, h1, l1);
                *(uint32_t*)(Ch + (size_t)m * ldc + n) = h0;
                *(uint32_t*)(Cl + (size_t)m * ldc + n) = l0;
                *(uint32_t*)(Ch + (size_t)(m + 8) * ldc + n) = h1;
                *(uint32_t*)(Cl + (size_t)(m + 8) * ldc + n) = l1;
            } else if (SPLIT == 3) {
                __half2 p0 = __floats2half2_rn(c0, c1);
                __half2 p1 = __floats2half2_rn(c2, c3);
                *(uint32_t*)(Ch + (size_t)m * ldc + n) = *(uint32_t*)&p0;
                *(uint32_t*)(Ch + (size_t)(m + 8) * ldc + n) = *(uint32_t*)&p1;
            } else {
                *(float2*)(Cf + (size_t)m * ldc + n) = make_float2(c0, c1);
                *(float2*)(Cf + (size_t)(m + 8) * ldc + n) = make_float2(c2, c3);
            }
        }
    }
}

// ---------------- merged linears: q, wk, vT in one launch ----------------
__global__ void __launch_bounds__(256)
linears_kernel(const __nv_bfloat16* __restrict__ xh,  const __nv_bfloat16* __restrict__ xl,
               const __nv_bfloat16* __restrict__ sh,  const __nv_bfloat16* __restrict__ sl,
               const __nv_bfloat16* __restrict__ Wqh, const __nv_bfloat16* __restrict__ Wql,
               const __nv_bfloat16* __restrict__ Weh, const __nv_bfloat16* __restrict__ Wel,
               const __nv_bfloat16* __restrict__ Wvh, const __nv_bfloat16* __restrict__ Wvl,
               __nv_bfloat16* qh, __nv_bfloat16* ql,
               __nv_bfloat16* wkh, __nv_bfloat16* wkl,
               __half* vT,
               const float* __restrict__ bq, const float* __restrict__ beff,
               const float* __restrict__ bv) {
    const int bid = blockIdx.x;
    if (bid < 512) {
        const __nv_bfloat16 *Ah, *Al, *Bh, *Bl;
        uint16_t *Ch, *Cl;
        const float* bias;
        int row0, col0;
        if (bid < 256) {        // q = x @ Wq^T + bq
            row0 = (bid & 127) * 128; col0 = (bid >> 7) * 128;
            Ah = xh; Al = xl; Bh = Wqh; Bl = Wql;
            Ch = (uint16_t*)qh; Cl = (uint16_t*)ql; bias = bq;
        } else {                // wk = states @ Weff^T + beff
            const int l = bid - 256;
            row0 = (l & 127) * 128; col0 = (l >> 7) * 128;
            Ah = sh; Al = sl; Bh = Weh; Bl = Wel;
            Ch = (uint16_t*)wkh; Cl = (uint16_t*)wkl; bias = beff;
        }
        gemm_body<1, DIM>(Ah, Al, Bh, Bl, nullptr, Ch, Cl, bias, 1,
                          DIM, DIM, DIM, row0, col0);
    } else {                    // vT = Wv @ states^T + bv (per batch), fp16 out
        const int l = bid - 512;
        const int bz = l >> 5, rem = l & 31;
        const int row0 = (rem & 1) * 128, col0 = (rem >> 1) * 128;
        gemm_body<3, DIM>(Wvh, Wvl,
                          sh + (size_t)bz * SK * DIM, sl + (size_t)bz * SK * DIM,
                          nullptr,
                          (uint16_t*)(vT + (size_t)bz * DIM * SK), nullptr,
                          bv, 2, DIM, DIM, SK, row0, col0);
    }
}

// ========== scores GEMM: fused 3-term single-pass chunks (k32) ============
// Stage (32KB): A tile 16KB (rows: Ah k32 bytes 0-63 | Al k32 bytes 64-127),
//               B tile 16KB (rows: Bh k32 | Bl k32). SW128 swizzle over the
//               full 128B row makes the interleave transparent to ldmatrix.
// Per chunk (k32 = 2 ks): Ah*Bh + Ah*Bl, then reuse a-regs for Al*Bh.
#define SC_STAGE 32768
__global__ void __launch_bounds__(256)
scores_kernel(const __nv_bfloat16* __restrict__ qh, const __nv_bfloat16* __restrict__ ql,
              const __nv_bfloat16* __restrict__ wkh, const __nv_bfloat16* __restrict__ wkl,
              float* __restrict__ sc) {
    extern __shared__ __align__(128) char smem[];
    const uint32_t sb = smem_u32(smem);
    const int tid = threadIdx.x, lane = tid & 31, wid = tid >> 5;
    const int row0 = blockIdx.x * 128, col0 = blockIdx.y * 128;
    const long long z = blockIdx.z;
    const __nv_bfloat16* Ah = qh  + z * SQ * DIM;
    const __nv_bfloat16* Al = ql  + z * SQ * DIM;
    const __nv_bfloat16* Bh = wkh + z * SK * DIM;
    const __nv_bfloat16* Bl = wkl + z * SK * DIM;
    float* Cf = sc + z * (size_t)SQ * SK;

    const int T = DIM >> 5;    // 8 chunks of k32
    const size_t ldby = (size_t)DIM * 2;

    // load one 8KB half-tile (128 rows x 64B) into byte-cols [colbase, colbase+64)
    auto load_half = [&](const char* g, uint32_t dst, int colbase) {
#pragma unroll
        for (int i = 0; i < 2; i++) {
            const int idx = i * 256 + tid;          // 0..511
            const int r = idx >> 2;                 // 0..127
            const int cl = (idx & 3) * 16;          // 0..48 within half
            const int c = cl + colbase;             // logical col in 128B row
            const uint32_t so = (uint32_t)(r * 128 + (c ^ ((r & 7) << 4)));
            CP_ASYNC16(dst + so, g + (size_t)r * ldby + cl);
        }
    };
    auto load_chunk = [&](int t, int p) {
        const uint32_t base = sb + p * SC_STAGE;
        const size_t ko = (size_t)t * 32;           // k-offset in elements
        load_half((const char*)(Ah + (size_t)row0 * DIM + ko), base, 0);
        load_half((const char*)(Al + (size_t)row0 * DIM + ko), base, 64);
        load_half((const char*)(Bh + (size_t)col0 * DIM + ko), base + 16384, 0);
        load_half((const char*)(Bl + (size_t)col0 * DIM + ko), base + 16384, 64);
        CP_COMMIT();
    };

    float acc[4][4][4];
#pragma unroll
    for (int i = 0; i < 4; i++)
#pragma unroll
        for (int j = 0; j < 4; j++)
#pragma unroll
            for (int e = 0; e < 4; e++) acc[i][j][e] = 0.f;

    const int wm0 = (wid & 1) * 64;
    const int wn0 = (wid >> 1) * 32;
    const uint32_t xr = (uint32_t)((lane & 7) << 4);
    const uint32_t aRow = (uint32_t)((wm0 + (lane & 15)) * 128);
    const uint32_t aK0  = (uint32_t)(((lane >> 4) & 1) * 16);
    const uint32_t bRow = (uint32_t)((wn0 + (((lane >> 3) & 2) << 2) + (lane & 7)) * 128);
    const uint32_t bK0  = (uint32_t)(((lane >> 3) & 1) * 16);

    auto compute = [&](int p) {
        const uint32_t smA = sb + p * SC_STAGE;
        const uint32_t smB = smA + 16384;
#pragma unroll
        for (int ks = 0; ks < 2; ks++) {
            uint32_t a[4][4], bh[2][4], bl[2][4];
            const uint32_t kh = aK0 + ks * 32;       // hi col 0..48
#pragma unroll
            for (int np = 0; np < 2; np++) {
                const uint32_t bo = bRow + np * 2048;
                const uint32_t kbh = bK0 + ks * 32;
                LDMATRIX_X4(bh[np][0], bh[np][1], bh[np][2], bh[np][3],
                            smB + bo + (kbh ^ xr));
                LDMATRIX_X4(bl[np][0], bl[np][1], bl[np][2], bl[np][3],
                            smB + bo + ((kbh + 64) ^ xr));
            }
#pragma unroll
            for (int mt = 0; mt < 4; mt++)
                LDMATRIX_X4(a[mt][0], a[mt][1], a[mt][2], a[mt][3],
                            smA + aRow + mt * 2048 + (kh ^ xr));
#pragma unroll
            for (int mt = 0; mt < 4; mt++)
#pragma unroll
                for (int nt = 0; nt < 4; nt++) {
                    MMA_BF16(acc[mt][nt], a[mt],
                             bh[nt >> 1][(nt & 1) * 2], bh[nt >> 1][(nt & 1) * 2 + 1]);
                    MMA_BF16(acc[mt][nt], a[mt],
                             bl[nt >> 1][(nt & 1) * 2], bl[nt >> 1][(nt & 1) * 2 + 1]);
                }
            // reuse a-regs for Al fragments
#pragma unroll
            for (int mt = 0; mt < 4; mt++)
                LDMATRIX_X4(a[mt][0], a[mt][1], a[mt][2], a[mt][3],
                            smA + aRow + mt * 2048 + ((kh + 64) ^ xr));
#pragma unroll
            for (int mt = 0; mt < 4; mt++)
#pragma unroll
                for (int nt = 0; nt < 4; nt++)
                    MMA_BF16(acc[mt][nt], a[mt],
                             bh[nt >> 1][(nt & 1) * 2], bh[nt >> 1][(nt & 1) * 2 + 1]);
        }
    };

    // two-bar runtime pipeline (proven regs<=128 shape)
    load_chunk(0, 0);
    for (int t = 0; t < T; t++) {
        const int p = t & 1;
        if (t + 1 < T) {
            load_chunk(t + 1, p ^ 1);
            CP_WAIT1();
        } else {
            CP_WAIT0();
        }
        __syncthreads();
        compute(p);
        __syncthreads();
    }

    const int bm = row0 + wm0 + (lane >> 2);
    const int bn = col0 + wn0 + (lane & 3) * 2;
#pragma unroll
    for (int mt = 0; mt < 4; mt++) {
#pragma unroll
        for (int nt = 0; nt < 4; nt++) {
            const int m = bm + mt * 16, n = bn + nt * 8;
            *(float2*)(Cf + (size_t)m * SK + n) =
                make_float2(acc[mt][nt][0], acc[mt][nt][1]);
            *(float2*)(Cf + (size_t)(m + 8) * SK + n) =
                make_float2(acc[mt][nt][2], acc[mt][nt][3]);
        }
    }
}

// -------- context GEMM: out = P @ vT^T  (single fp16 term, R9 body) ------
__global__ void __launch_bounds__(256)
ctx_kernel(const __half* __restrict__ P, const __half* __restrict__ V,
           float* __restrict__ out) {
    extern __shared__ __align__(128) char smem[];
    const uint32_t sb = smem_u32(smem);
    const int tid = threadIdx.x, lane = tid & 31, wid = tid >> 5;
    const int row0 = blockIdx.x * 128, col0 = blockIdx.y * 128;
    const long long z = blockIdx.z;
    P  += z * (size_t)SQ * SK;
    V  += z * (size_t)DIM * SK;
    out += z * (size_t)SQ * DIM;

    constexpr int KT = SK >> 6;   // 32 chunks
    const size_t ldby = (size_t)SK * 2;

    auto load_one = [&](const char* g, uint32_t dst) {
#pragma unroll
        for (int i = 0; i < 4; i++) {
            const int idx = i * 256 + tid;
            const int r = idx >> 3, c = (idx & 7) * 16;
            const uint32_t so = (uint32_t)(r * 128 + (c ^ ((r & 7) << 4)));
            CP_ASYNC16(dst + so, g + (size_t)r * ldby + c);
        }
    };
    auto load_chunk = [&](int t, int p) {
        const uint32_t base = sb + p * STAGE_BYTES;
        load_one((const char*)(P + (size_t)row0 * SK + t * 64), base);
        load_one((const char*)(V + (size_t)col0 * SK + t * 64), base + 16384);
        CP_COMMIT();
    };

    float acc[4][4][4];
#pragma unroll
    for (int i = 0; i < 4; i++)
#pragma unroll
        for (int j = 0; j < 4; j++)
#pragma unroll
            for (int e = 0; e < 4; e++) acc[i][j][e] = 0.f;

    const int wm0 = (wid & 1) * 64;
    const int wn0 = (wid >> 1) * 32;
    const uint32_t xr = (uint32_t)((lane & 7) << 4);
    const uint32_t aRow = (uint32_t)((wm0 + (lane & 15)) * 128);
    const uint32_t aK0  = (uint32_t)(((lane >> 4) & 1) * 16);
    const uint32_t bRow = (uint32_t)((wn0 + (((lane >> 3) & 2) << 2) + (lane & 7)) * 128);
    const uint32_t bK0  = (uint32_t)(((lane >> 3) & 1) * 16);

    auto compute = [&](int p) {
        const uint32_t smA = sb + p * STAGE_BYTES;
        const uint32_t smB = smA + 16384;
#pragma unroll
        for (int ks = 0; ks < 4; ks++) {
            uint32_t a[4][4], b[2][4];
#pragma unroll
            for (int mt = 0; mt < 4; mt++) {
                const uint32_t ad = smA + aRow + mt * 2048 + ((aK0 + ks * 32) ^ xr);
                LDMATRIX_X4(a[mt][0], a[mt][1], a[mt][2], a[mt][3], ad);
            }
#pragma unroll
            for (int np = 0; np < 2; np++) {
                const uint32_t bd = smB + bRow + np * 2048 + ((bK0 + ks * 32) ^ xr);
                LDMATRIX_X4(b[np][0], b[np][1], b[np][2], b[np][3], bd);
            }
#pragma unroll
            for (int mt = 0; mt < 4; mt++)
#pragma unroll
                for (int nt = 0; nt < 4; nt++)
                    MMA_F16(acc[mt][nt], a[mt],
                            b[nt >> 1][(nt & 1) * 2], b[nt >> 1][(nt & 1) * 2 + 1]);
        }
    };

    // single-bar pipeline
    load_chunk(0, 0);
#pragma unroll
    for (int t = 0; t < KT; t++) {
        const int p = t & 1;
        CP_WAIT0();
        __syncthreads();
        if (t + 1 < KT) load_chunk(t + 1, p ^ 1);
        compute(p);
    }

    const int bm = row0 + wm0 + (lane >> 2);
    const int bn = col0 + wn0 + (lane & 3) * 2;
#pragma unroll
    for (int mt = 0; mt < 4; mt++) {
#pragma unroll
        for (int nt = 0; nt < 4; nt++) {
            const int m = bm + mt * 16, n = bn + nt * 8;
            *(float2*)(out + (size_t)m * DIM + n) =
                make_float2(acc[mt][nt][0], acc[mt][nt][1]);
            *(float2*)(out + (size_t)(m + 8) * DIM + n) =
                make_float2(acc[mt][nt][2], acc[mt][nt][3]);
        }
    }
}

// ---------------- fused-weight prep: Weff = Wa @ Wk (bf16-split out) ------
__global__ void weff_kernel(const float* __restrict__ Wa,
                            const float* __restrict__ Wk,
                            const float* __restrict__ bk,
                            const float* __restrict__ ba,
                            __nv_bfloat16* __restrict__ Weh,
                            __nv_bfloat16* __restrict__ Wel,
                            float* __restrict__ beff) {
    const int e = blockIdx.x;
    const int t = threadIdx.x;
    __shared__ float wa[DIM];
    wa[t] = Wa[e * DIM + t];
    __syncthreads();
    float acc = 0.f;
#pragma unroll 8
    for (int j = 0; j < DIM; j++)
        acc = fmaf(wa[j], Wk[j * DIM + t], acc);
    __nv_bfloat16 hi = __float2bfloat16(acc);
    Weh[e * DIM + t] = hi;
    Wel[e * DIM + t] = __float2bfloat16(acc - __bfloat162float(hi));

    float pb = wa[t] * bk[t];
#pragma unroll
    for (int o = 16; o; o >>= 1)
        pb += __shfl_xor_sync(0xffffffffu, pb, o);
    __shared__ float red[8];
    if ((t & 31) == 0) red[t >> 5] = pb;
    __syncthreads();
    if (t == 0) {
        float s = 0.f;
#pragma unroll
        for (int i = 0; i < 8; i++) s += red[i];
        beff[e] = s + ba[e];
    }
}

// ---------------- merged fp32 -> (hi,lo) bf16 split for 4 tensors ----------
#define NB_ACT (MQ * DIM / 4 / 256)     // 4096 blocks per activation tensor
#define NB_W   (DIM * DIM / 4 / 256)    // 64 blocks per weight
__global__ void split4_kernel(const float* __restrict__ x,   __nv_bfloat16* xh, __nv_bfloat16* xl,
                              const float* __restrict__ st,  __nv_bfloat16* sh, __nv_bfloat16* sl,
                              const float* __restrict__ wq,  __nv_bfloat16* qh, __nv_bfloat16* ql,
                              const float* __restrict__ wv,  __nv_bfloat16* vh, __nv_bfloat16* vl) {
    int b = blockIdx.x;
    const float* in; __nv_bfloat16 *h, *l;
    if (b < NB_ACT)                   { in = x;  h = xh; l = xl; }
    else if ((b -= NB_ACT) < NB_ACT)  { in = st; h = sh; l = sl; }
    else if ((b -= NB_ACT) < NB_W)    { in = wq; h = qh; l = ql; }
    else { b -= NB_W;                   in = wv; h = vh; l = vl; }
    const size_t i = (size_t)b * 256 + threadIdx.x;
    float4 v = *(const float4*)(in + 4 * i);
    uint32_t h0, l0, h1, l1;
    splitpair_bf(v.x, v.y, h0, l0);
    splitpair_bf(v.z, v.w, h1, l1);
    *(uint2*)(h + 4 * i) = make_uint2(h0, h1);
    *(uint2*)(l + 4 * i) = make_uint2(l0, l1);
}

// -------- softmax over 2048-wide rows (256 thr, R9 version) ---------------
__global__ void softmax_p(const float* __restrict__ S, __half* __restrict__ P) {
    const size_t row = blockIdx.x;
    const float4* p4 = (const float4*)(S + row * (size_t)SK);
    const int t = threadIdx.x;

    float4 u0 = p4[t];
    float4 u1 = p4[t + 256];
    float v[8] = {u0.x, u0.y, u0.z, u0.w, u1.x, u1.y, u1.z, u1.w};

    float m = v[0];
#pragma unroll
    for (int i = 1; i < 8; i++) m = fmaxf(m, v[i]);
#pragma unroll
    for (int o = 16; o; o >>= 1) m = fmaxf(m, __shfl_xor_sync(0xffffffffu, m, o));

    __shared__ float red[8];
    const int w = t >> 5, l = t & 31;
    if (l == 0) red[w] = m;
    __syncthreads();
    float mm = red[0];
#pragma unroll
    for (int i = 1; i < 8; i++) mm = fmaxf(mm, red[i]);

    float s = 0.f;
#pragma unroll
    for (int i = 0; i < 8; i++) {
        v[i] = __expf(v[i] - mm);
        s += v[i];
    }
#pragma unroll
    for (int o = 16; o; o >>= 1) s += __shfl_xor_sync(0xffffffffu, s, o);
    __syncthreads();
    if (l == 0) red[w] = s;
    __syncthreads();
    float ss = red[0];
#pragma unroll
    for (int i = 1; i < 8; i++) ss += red[i];
    const float inv = 1.0f / ss;

    __half* bp = P + row * (size_t)SK;
#pragma unroll
    for (int half = 0; half < 2; half++) {
        const int c = (half ? (t + 256) : t) * 4;
        __half2 h0 = __floats2half2_rn(v[half * 4 + 0] * inv, v[half * 4 + 1] * inv);
        __half2 h1 = __floats2half2_rn(v[half * 4 + 2] * inv, v[half * 4 + 3] * inv);
        *(uint2*)(bp + c) = make_uint2(*(uint32_t*)&h0, *(uint32_t*)&h1);
    }
}

// ---------------- launcher ----------------
extern "C" void kernel_launch(void* const* d_in, const int* in_sizes, int n_in,
                              void* d_out, int out_size) {
    const float* x      = (const float*)d_in[0];
    const float* states = (const float*)d_in[1];
    const float* Wq = (const float*)d_in[2];
    const float* bq = (const float*)d_in[3];
    const float* Wk = (const float*)d_in[4];
    const float* bk = (const float*)d_in[5];
    const float* Wv = (const float*)d_in[6];
    const float* bv = (const float*)d_in[7];
    const float* Wa = (const float*)d_in[8];
    const float* ba = (const float*)d_in[9];
    float* out = (float*)d_out;

    float *sc, *beff;
    __nv_bfloat16 *xh, *xl, *sh, *sl, *Wqh, *Wql, *Weh, *Wel, *Wvh, *Wvl;
    __nv_bfloat16 *qh, *ql, *wkh, *wkl;
    __half *vT, *P;
    cudaGetSymbolAddress((void**)&sc,   g_scores);
    cudaGetSymbolAddress((void**)&beff, g_beff);
    cudaGetSymbolAddress((void**)&xh,  g_xh);   cudaGetSymbolAddress((void**)&xl,  g_xl);
    cudaGetSymbolAddress((void**)&sh,  g_sh);   cudaGetSymbolAddress((void**)&sl,  g_sl);
    cudaGetSymbolAddress((void**)&Wqh, g_Wqh);  cudaGetSymbolAddress((void**)&Wql, g_Wql);
    cudaGetSymbolAddress((void**)&Weh, g_Weh);  cudaGetSymbolAddress((void**)&Wel, g_Wel);
    cudaGetSymbolAddress((void**)&Wvh, g_Wvh);  cudaGetSymbolAddress((void**)&Wvl, g_Wvl);
    cudaGetSymbolAddress((void**)&qh,  g_qh);   cudaGetSymbolAddress((void**)&ql,  g_ql);
    cudaGetSymbolAddress((void**)&wkh, g_wkh);  cudaGetSymbolAddress((void**)&wkl, g_wkl);
    cudaGetSymbolAddress((void**)&vT,  g_vT);
    cudaGetSymbolAddress((void**)&P,   g_P);

    cudaFuncSetAttribute(linears_kernel, cudaFuncAttributeMaxDynamicSharedMemorySize, SMEM_BYTES);
    cudaFuncSetAttribute(scores_kernel,  cudaFuncAttributeMaxDynamicSharedMemorySize, SMEM_BYTES);
    cudaFuncSetAttribute(ctx_kernel,     cudaFuncAttributeMaxDynamicSharedMemorySize, SMEM_BYTES);

    // 1) fold Wa into the K projection (fp32 -> split bf16 directly)
    weff_kernel<<<DIM, DIM>>>(Wa, Wk, bk, ba, Weh, Wel, beff);

    // 2) bf16 splits of x, states, Wq, Wv
    split4_kernel<<<2 * NB_ACT + 2 * NB_W, 256>>>(
        x, xh, xl, states, sh, sl, Wq, Wqh, Wql, Wv, Wvh, Wvl);

    // 3) all three linears in ONE launch (768 CTAs); vT emitted as single fp16
    linears_kernel<<<768, 256, SMEM_BYTES>>>(
        xh, xl, sh, sl, Wqh, Wql, Weh, Wel, Wvh, Wvl,
        qh, ql, wkh, wkl, vT, bq, beff, bv);

    // 4) scores = q @ wk^T per batch (fused 3-term, k32 chunks), fp32 out
    scores_kernel<<<dim3(SQ / 128, SK / 128, BATCH), 256, 2 * SC_STAGE>>>(
        qh, ql, wkh, wkl, sc);

    // 5) softmax -> single fp16 P (256 threads/row)
    softmax_p<<<MQ, 256>>>(sc, P);

    // 6) context = P @ vT^T per batch (single fp16 term) -> fp32 out
    ctx_kernel<<<dim3(SQ / 128, DIM / 128, BATCH), 256, SMEM_BYTES>>>(
        P, vT, out);
}

// round 14
// speedup vs baseline: 1.0411x; 1.0411x over previous
#include <cuda_runtime.h>
#include <cuda_bf16.h>
#include <cuda_fp16.h>
#include <cstdint>
#include <math_constants.h>

#define BATCH 8
#define SQ    2048
#define SK    2048
#define DIM   256
#define MQ    (BATCH*SQ)

// ---------------- scratch (device globals; no runtime allocation) ----------
__device__ float g_scores[(size_t)BATCH * SQ * SK];
__device__ float g_beff[DIM];

__device__ __nv_bfloat16 g_xh[MQ * DIM],  g_xl[MQ * DIM];
__device__ __nv_bfloat16 g_sh[MQ * DIM],  g_sl[MQ * DIM];
__device__ __nv_bfloat16 g_Wqh[DIM * DIM], g_Wql[DIM * DIM];
__device__ __nv_bfloat16 g_Weh[DIM * DIM], g_Wel[DIM * DIM];
__device__ __nv_bfloat16 g_Wvh[DIM * DIM], g_Wvl[DIM * DIM];
__device__ __nv_bfloat16 g_qh[MQ * DIM],  g_ql[MQ * DIM];
__device__ __nv_bfloat16 g_wkh[MQ * DIM], g_wkl[MQ * DIM];
__device__ __half g_vT[BATCH * DIM * SK];

// ---------------- helpers ----------------
__device__ __forceinline__ uint32_t smem_u32(const void* p) {
    uint32_t a;
    asm("{ .reg .u64 t; cvta.to.shared.u64 t, %1; cvt.u32.u64 %0, t; }"
        : "=r"(a) : "l"(p));
    return a;
}

__device__ __forceinline__ void splitpair_bf(float a, float b, uint32_t& h, uint32_t& l) {
    __nv_bfloat16 ha = __float2bfloat16(a), hb = __float2bfloat16(b);
    float la = a - __bfloat162float(ha);
    float lb = b - __bfloat162float(hb);
    h = (uint32_t)__bfloat16_as_ushort(ha) | ((uint32_t)__bfloat16_as_ushort(hb) << 16);
    l = (uint32_t)__bfloat16_as_ushort(__float2bfloat16(la)) |
        ((uint32_t)__bfloat16_as_ushort(__float2bfloat16(lb)) << 16);
}

#define CP_ASYNC16(dst, src) \
    asm volatile("cp.async.cg.shared.global [%0], [%1], 16;" \
                 :: "r"(dst), "l"(src) : "memory")
#define CP_COMMIT() asm volatile("cp.async.commit_group;" ::: "memory")
#define CP_WAIT1()  asm volatile("cp.async.wait_group 1;" ::: "memory")
#define CP_WAIT0()  asm volatile("cp.async.wait_group 0;" ::: "memory")

#define LDMATRIX_X4(r0, r1, r2, r3, addr)                                     \
    asm volatile("ldmatrix.sync.aligned.m8n8.x4.shared.b16 {%0,%1,%2,%3}, [%4];" \
                 : "=r"(r0), "=r"(r1), "=r"(r2), "=r"(r3) : "r"(addr))

#define MMA_BF16(c, a, b0, b1)                                                \
    asm volatile("mma.sync.aligned.m16n8k16.row.col.f32.bf16.bf16.f32 "       \
                 "{%0,%1,%2,%3}, {%4,%5,%6,%7}, {%8,%9}, {%0,%1,%2,%3};"      \
                 : "+f"((c)[0]), "+f"((c)[1]), "+f"((c)[2]), "+f"((c)[3])     \
                 : "r"((a)[0]), "r"((a)[1]), "r"((a)[2]), "r"((a)[3]),        \
                   "r"(b0), "r"(b1))

#define MMA_F16(c, a, b0, b1)                                                 \
    asm volatile("mma.sync.aligned.m16n8k16.row.col.f32.f16.f16.f32 "         \
                 "{%0,%1,%2,%3}, {%4,%5,%6,%7}, {%8,%9}, {%0,%1,%2,%3};"      \
                 : "+f"((c)[0]), "+f"((c)[1]), "+f"((c)[2]), "+f"((c)[3])     \
                 : "r"((a)[0]), "r"((a)[1]), "r"((a)[2]), "r"((a)[3]),        \
                   "r"(b0), "r"(b1))

// 2 stages; each stage = up to 3 slots of 16KB (linears/scores bodies)
#define STAGE_BYTES 49152
#define SMEM_BYTES  98304

// ================= bf16-split GEMM body (R9: single-bar, unrolled) ========
template <int SPLIT, int K>
__device__ __forceinline__ void gemm_body(
    const __nv_bfloat16* __restrict__ Ah, const __nv_bfloat16* __restrict__ Al,
    const __nv_bfloat16* __restrict__ Bh, const __nv_bfloat16* __restrict__ Bl,
    float* __restrict__ Cf, uint16_t* __restrict__ Ch,
    uint16_t* __restrict__ Cl, const float* __restrict__ bias,
    int biasMode, int lda, int ldb, int ldc, int row0, int col0)
{
    extern __shared__ __align__(128) char smem[];
    const uint32_t sb = smem_u32(smem);
    const int tid = threadIdx.x, lane = tid & 31, wid = tid >> 5;

    constexpr int KT = K >> 6;
    constexpr int T  = 2 * KT;
    const size_t ldaby = (size_t)lda * 2;
    const size_t ldbby = (size_t)ldb * 2;

    auto load_one = [&](const char* g, size_t ldby, uint32_t dst) {
#pragma unroll
        for (int i = 0; i < 4; i++) {
            const int idx = i * 256 + tid;
            const int r = idx >> 3, c = (idx & 7) * 16;
            const uint32_t so = (uint32_t)(r * 128 + (c ^ ((r & 7) << 4)));
            CP_ASYNC16(dst + so, g + (size_t)r * ldby + c);
        }
    };
    auto load_chunk = [&](int t, int p) {
        const uint32_t base = sb + p * STAGE_BYTES;
        if (t < KT) {
            const int kt = t;
            load_one((const char*)(Ah + (size_t)row0 * lda + kt * 64), ldaby, base);
            load_one((const char*)(Bh + (size_t)col0 * ldb + kt * 64), ldbby, base + 16384);
            load_one((const char*)(Bl + (size_t)col0 * ldb + kt * 64), ldbby, base + 32768);
        } else {
            const int kt = t - KT;
            load_one((const char*)(Al + (size_t)row0 * lda + kt * 64), ldaby, base);
            load_one((const char*)(Bh + (size_t)col0 * ldb + kt * 64), ldbby, base + 16384);
        }
        CP_COMMIT();
    };

    float acc[4][4][4];
#pragma unroll
    for (int i = 0; i < 4; i++)
#pragma unroll
        for (int j = 0; j < 4; j++)
#pragma unroll
            for (int e = 0; e < 4; e++) acc[i][j][e] = 0.f;

    const int wm0 = (wid & 1) * 64;
    const int wn0 = (wid >> 1) * 32;
    const uint32_t xr = (uint32_t)((lane & 7) << 4);
    const uint32_t aRow = (uint32_t)((wm0 + (lane & 15)) * 128);
    const uint32_t aK0  = (uint32_t)(((lane >> 4) & 1) * 16);
    const uint32_t bRow = (uint32_t)((wn0 + (((lane >> 3) & 2) << 2) + (lane & 7)) * 128);
    const uint32_t bK0  = (uint32_t)(((lane >> 3) & 1) * 16);

    auto compute1 = [&](int p) {
        const uint32_t smA  = sb + p * STAGE_BYTES;
        const uint32_t smBh = smA + 16384;
        const uint32_t smBl = smA + 32768;
#pragma unroll
        for (int ks = 0; ks < 4; ks++) {
            uint32_t a[4][4], bh[2][4], bl[2][4];
#pragma unroll
            for (int mt = 0; mt < 4; mt++) {
                const uint32_t ad = smA + aRow + mt * 2048 + ((aK0 + ks * 32) ^ xr);
                LDMATRIX_X4(a[mt][0], a[mt][1], a[mt][2], a[mt][3], ad);
            }
#pragma unroll
            for (int np = 0; np < 2; np++) {
                const uint32_t off = bRow + np * 2048 + ((bK0 + ks * 32) ^ xr);
                LDMATRIX_X4(bh[np][0], bh[np][1], bh[np][2], bh[np][3], smBh + off);
                LDMATRIX_X4(bl[np][0], bl[np][1], bl[np][2], bl[np][3], smBl + off);
            }
#pragma unroll
            for (int mt = 0; mt < 4; mt++)
#pragma unroll
                for (int nt = 0; nt < 4; nt++) {
                    MMA_BF16(acc[mt][nt], a[mt],
                             bh[nt >> 1][(nt & 1) * 2], bh[nt >> 1][(nt & 1) * 2 + 1]);
                    MMA_BF16(acc[mt][nt], a[mt],
                             bl[nt >> 1][(nt & 1) * 2], bl[nt >> 1][(nt & 1) * 2 + 1]);
                }
        }
    };
    auto compute2 = [&](int p) {
        const uint32_t smA  = sb + p * STAGE_BYTES;
        const uint32_t smBh = smA + 16384;
#pragma unroll
        for (int ks = 0; ks < 4; ks++) {
            uint32_t a[4][4], b[2][4];
#pragma unroll
            for (int mt = 0; mt < 4; mt++) {
                const uint32_t ad = smA + aRow + mt * 2048 + ((aK0 + ks * 32) ^ xr);
                LDMATRIX_X4(a[mt][0], a[mt][1], a[mt][2], a[mt][3], ad);
            }
#pragma unroll
            for (int np = 0; np < 2; np++) {
                const uint32_t bd = smBh + bRow + np * 2048 + ((bK0 + ks * 32) ^ xr);
                LDMATRIX_X4(b[np][0], b[np][1], b[np][2], b[np][3], bd);
            }
#pragma unroll
            for (int mt = 0; mt < 4; mt++)
#pragma unroll
                for (int nt = 0; nt < 4; nt++)
                    MMA_BF16(acc[mt][nt], a[mt],
                             b[nt >> 1][(nt & 1) * 2], b[nt >> 1][(nt & 1) * 2 + 1]);
        }
    };

    load_chunk(0, 0);
#pragma unroll
    for (int t = 0; t < T; t++) {
        const int p = t & 1;
        CP_WAIT0();
        __syncthreads();
        if (t + 1 < T) load_chunk(t + 1, p ^ 1);
        if (t < KT) compute1(p); else compute2(p);
    }

    const int bm = row0 + wm0 + (lane >> 2);
    const int bn = col0 + wn0 + (lane & 3) * 2;
#pragma unroll
    for (int mt = 0; mt < 4; mt++) {
#pragma unroll
        for (int nt = 0; nt < 4; nt++) {
            const int m = bm + mt * 16, n = bn + nt * 8;
            float c0 = acc[mt][nt][0], c1 = acc[mt][nt][1];
            float c2 = acc[mt][nt][2], c3 = acc[mt][nt][3];
            if (biasMode == 1) {
                const float b0v = bias[n], b1v = bias[n + 1];
                c0 += b0v; c1 += b1v; c2 += b0v; c3 += b1v;
            } else if (biasMode == 2) {
                c0 += bias[m]; c1 += bias[m];
                c2 += bias[m + 8]; c3 += bias[m + 8];
            }
            if (SPLIT == 1) {
                uint32_t h0, l0, h1, l1;
                splitpair_bf(c0, c1, h0, l0);
                splitpair_bf(c2, c3, h1, l1);
                *(uint32_t*)(Ch + (size_t)m * ldc + n) = h0;
                *(uint32_t*)(Cl + (size_t)m * ldc + n) = l0;
                *(uint32_t*)(Ch + (size_t)(m + 8) * ldc + n) = h1;
                *(uint32_t*)(Cl + (size_t)(m + 8) * ldc + n) = l1;
            } else if (SPLIT == 3) {
                __half2 p0 = __floats2half2_rn(c0, c1);
                __half2 p1 = __floats2half2_rn(c2, c3);
                *(uint32_t*)(Ch + (size_t)m * ldc + n) = *(uint32_t*)&p0;
                *(uint32_t*)(Ch + (size_t)(m + 8) * ldc + n) = *(uint32_t*)&p1;
            } else {
                *(float2*)(Cf + (size_t)m * ldc + n) = make_float2(c0, c1);
                *(float2*)(Cf + (size_t)(m + 8) * ldc + n) = make_float2(c2, c3);
            }
        }
    }
}

// ---------------- merged linears: q, wk, vT in one launch ----------------
__global__ void __launch_bounds__(256)
linears_kernel(const __nv_bfloat16* __restrict__ xh,  const __nv_bfloat16* __restrict__ xl,
               const __nv_bfloat16* __restrict__ sh,  const __nv_bfloat16* __restrict__ sl,
               const __nv_bfloat16* __restrict__ Wqh, const __nv_bfloat16* __restrict__ Wql,
               const __nv_bfloat16* __restrict__ Weh, const __nv_bfloat16* __restrict__ Wel,
               const __nv_bfloat16* __restrict__ Wvh, const __nv_bfloat16* __restrict__ Wvl,
               __nv_bfloat16* qh, __nv_bfloat16* ql,
               __nv_bfloat16* wkh, __nv_bfloat16* wkl,
               __half* vT,
               const float* __restrict__ bq, const float* __restrict__ beff,
               const float* __restrict__ bv) {
    const int bid = blockIdx.x;
    if (bid < 512) {
        const __nv_bfloat16 *Ah, *Al, *Bh, *Bl;
        uint16_t *Ch, *Cl;
        const float* bias;
        int row0, col0;
        if (bid < 256) {
            row0 = (bid & 127) * 128; col0 = (bid >> 7) * 128;
            Ah = xh; Al = xl; Bh = Wqh; Bl = Wql;
            Ch = (uint16_t*)qh; Cl = (uint16_t*)ql; bias = bq;
        } else {
            const int l = bid - 256;
            row0 = (l & 127) * 128; col0 = (l >> 7) * 128;
            Ah = sh; Al = sl; Bh = Weh; Bl = Wel;
            Ch = (uint16_t*)wkh; Cl = (uint16_t*)wkl; bias = beff;
        }
        gemm_body<1, DIM>(Ah, Al, Bh, Bl, nullptr, Ch, Cl, bias, 1,
                          DIM, DIM, DIM, row0, col0);
    } else {
        const int l = bid - 512;
        const int bz = l >> 5, rem = l & 31;
        const int row0 = (rem & 1) * 128, col0 = (rem >> 1) * 128;
        gemm_body<3, DIM>(Wvh, Wvl,
                          sh + (size_t)bz * SK * DIM, sl + (size_t)bz * SK * DIM,
                          nullptr,
                          (uint16_t*)(vT + (size_t)bz * DIM * SK), nullptr,
                          bv, 2, DIM, DIM, SK, row0, col0);
    }
}

// ========== scores GEMM: R11 proven two-bar runtime-K body =================
__global__ void __launch_bounds__(256)
scores_kernel(const __nv_bfloat16* __restrict__ qh, const __nv_bfloat16* __restrict__ ql,
              const __nv_bfloat16* __restrict__ wkh, const __nv_bfloat16* __restrict__ wkl,
              float* __restrict__ sc) {
    extern __shared__ __align__(128) char smem[];
    const uint32_t sb = smem_u32(smem);
    const int tid = threadIdx.x, lane = tid & 31, wid = tid >> 5;
    const int row0 = blockIdx.x * 128, col0 = blockIdx.y * 128;
    const long long z = blockIdx.z;
    const __nv_bfloat16* Ah = qh  + z * SQ * DIM;
    const __nv_bfloat16* Al = ql  + z * SQ * DIM;
    const __nv_bfloat16* Bh = wkh + z * SK * DIM;
    const __nv_bfloat16* Bl = wkl + z * SK * DIM;
    float* Cf = sc + z * (size_t)SQ * SK;

    const int KT = DIM >> 6;   // 4
    const int T  = 2 * KT;     // 8
    const size_t ldby = (size_t)DIM * 2;

    auto load_one = [&](const char* g, uint32_t dst) {
#pragma unroll
        for (int i = 0; i < 4; i++) {
            const int idx = i * 256 + tid;
            const int r = idx >> 3, c = (idx & 7) * 16;
            const uint32_t so = (uint32_t)(r * 128 + (c ^ ((r & 7) << 4)));
            CP_ASYNC16(dst + so, g + (size_t)r * ldby + c);
        }
    };
    auto load_chunk = [&](int t, int p) {
        const uint32_t base = sb + p * STAGE_BYTES;
        if (t < KT) {
            load_one((const char*)(Ah + (size_t)row0 * DIM + t * 64), base);
            load_one((const char*)(Bh + (size_t)col0 * DIM + t * 64), base + 16384);
            load_one((const char*)(Bl + (size_t)col0 * DIM + t * 64), base + 32768);
        } else {
            const int kt = t - KT;
            load_one((const char*)(Al + (size_t)row0 * DIM + kt * 64), base);
            load_one((const char*)(Bh + (size_t)col0 * DIM + kt * 64), base + 16384);
        }
        CP_COMMIT();
    };

    float acc[4][4][4];
#pragma unroll
    for (int i = 0; i < 4; i++)
#pragma unroll
        for (int j = 0; j < 4; j++)
#pragma unroll
            for (int e = 0; e < 4; e++) acc[i][j][e] = 0.f;

    const int wm0 = (wid & 1) * 64;
    const int wn0 = (wid >> 1) * 32;
    const uint32_t xr = (uint32_t)((lane & 7) << 4);
    const uint32_t aRow = (uint32_t)((wm0 + (lane & 15)) * 128);
    const uint32_t aK0  = (uint32_t)(((lane >> 4) & 1) * 16);
    const uint32_t bRow = (uint32_t)((wn0 + (((lane >> 3) & 2) << 2) + (lane & 7)) * 128);
    const uint32_t bK0  = (uint32_t)(((lane >> 3) & 1) * 16);

    auto compute1 = [&](int p) {
        const uint32_t smA  = sb + p * STAGE_BYTES;
        const uint32_t smBh = smA + 16384;
        const uint32_t smBl = smA + 32768;
#pragma unroll
        for (int ks = 0; ks < 4; ks++) {
            uint32_t a[4][4], bh[2][4], bl[2][4];
#pragma unroll
            for (int mt = 0; mt < 4; mt++) {
                const uint32_t ad = smA + aRow + mt * 2048 + ((aK0 + ks * 32) ^ xr);
                LDMATRIX_X4(a[mt][0], a[mt][1], a[mt][2], a[mt][3], ad);
            }
#pragma unroll
            for (int np = 0; np < 2; np++) {
                const uint32_t off = bRow + np * 2048 + ((bK0 + ks * 32) ^ xr);
                LDMATRIX_X4(bh[np][0], bh[np][1], bh[np][2], bh[np][3], smBh + off);
                LDMATRIX_X4(bl[np][0], bl[np][1], bl[np][2], bl[np][3], smBl + off);
            }
#pragma unroll
            for (int mt = 0; mt < 4; mt++)
#pragma unroll
                for (int nt = 0; nt < 4; nt++) {
                    MMA_BF16(acc[mt][nt], a[mt],
                             bh[nt >> 1][(nt & 1) * 2], bh[nt >> 1][(nt & 1) * 2 + 1]);
                    MMA_BF16(acc[mt][nt], a[mt],
                             bl[nt >> 1][(nt & 1) * 2], bl[nt >> 1][(nt & 1) * 2 + 1]);
                }
        }
    };
    auto compute2 = [&](int p) {
        const uint32_t smA  = sb + p * STAGE_BYTES;
        const uint32_t smBh = smA + 16384;
#pragma unroll
        for (int ks = 0; ks < 4; ks++) {
            uint32_t a[4][4], b[2][4];
#pragma unroll
            for (int mt = 0; mt < 4; mt++) {
                const uint32_t ad = smA + aRow + mt * 2048 + ((aK0 + ks * 32) ^ xr);
                LDMATRIX_X4(a[mt][0], a[mt][1], a[mt][2], a[mt][3], ad);
            }
#pragma unroll
            for (int np = 0; np < 2; np++) {
                const uint32_t bd = smBh + bRow + np * 2048 + ((bK0 + ks * 32) ^ xr);
                LDMATRIX_X4(b[np][0], b[np][1], b[np][2], b[np][3], bd);
            }
#pragma unroll
            for (int mt = 0; mt < 4; mt++)
#pragma unroll
                for (int nt = 0; nt < 4; nt++)
                    MMA_BF16(acc[mt][nt], a[mt],
                             b[nt >> 1][(nt & 1) * 2], b[nt >> 1][(nt & 1) * 2 + 1]);
        }
    };

    load_chunk(0, 0);
    for (int t = 0; t < T; t++) {
        const int p = t & 1;
        if (t + 1 < T) {
            load_chunk(t + 1, p ^ 1);
            CP_WAIT1();
        } else {
            CP_WAIT0();
        }
        __syncthreads();
        if (t < KT) compute1(p); else compute2(p);
        __syncthreads();
    }

    const int bm = row0 + wm0 + (lane >> 2);
    const int bn = col0 + wn0 + (lane & 3) * 2;
#pragma unroll
    for (int mt = 0; mt < 4; mt++) {
#pragma unroll
        for (int nt = 0; nt < 4; nt++) {
            const int m = bm + mt * 16, n = bn + nt * 8;
            *(float2*)(Cf + (size_t)m * SK + n) =
                make_float2(acc[mt][nt][0], acc[mt][nt][1]);
            *(float2*)(Cf + (size_t)(m + 8) * SK + n) =
                make_float2(acc[mt][nt][2], acc[mt][nt][3]);
        }
    }
}

// ===== flash-style fused softmax + context (FIXED pipeline) ================
// One CTA = 64 q-rows x all 256 out cols, one batch. 32 chunks of k64.
// Per chunk: convert S -> unnormalized fp16 P[pb] + fFac[pb] (double-buffered),
// wait V(t), ONE bar, load V(t+1) (one ahead only), rescale acc, MMA.
// smem: V[2][32KB] + P[2][8KB] + fFac[2][64] + fZ[64]
#define FC_VST 32768
#define FC_PST 8192
#define FC_SMEM (2*FC_VST + 2*FC_PST + 1024)
__global__ void __launch_bounds__(256)
flash_ctx_kernel(const float* __restrict__ S, const __half* __restrict__ V,
                 float* __restrict__ out) {
    extern __shared__ __align__(128) char smem[];
    const uint32_t sb = smem_u32(smem);
    const int tid = threadIdx.x, lane = tid & 31, wid = tid >> 5;
    const int row0 = blockIdx.x * 64;
    const long long z = blockIdx.z;
    S   += z * (size_t)SQ * SK + (size_t)row0 * SK;
    V   += z * (size_t)DIM * SK;
    out += z * (size_t)SQ * DIM + (size_t)row0 * DIM;

    const uint32_t smV = sb;
    const uint32_t smP = sb + 2 * FC_VST;
    float* fFac = (float*)(smem + 2 * FC_VST + 2 * FC_PST);  // [2][64]
    float* fZ   = fFac + 128;                                 // [64]

    constexpr int T = SK >> 6;   // 32 chunks of k64
    const size_t vldby = (size_t)SK * 2;

    auto load_V = [&](int t, int buf) {
        const char* g = (const char*)V + (size_t)t * 128;
        const uint32_t dst = smV + buf * FC_VST;
#pragma unroll
        for (int i = 0; i < 8; i++) {
            const int idx = i * 256 + tid;
            const int r = idx >> 3, c = (idx & 7) * 16;
            const uint32_t so = (uint32_t)(r * 128 + (c ^ ((r & 7) << 4)));
            CP_ASYNC16(dst + so, g + (size_t)r * vldby + c);
        }
        CP_COMMIT();
    };

    // conversion: quad (4 threads) per row; 16 S values per thread per chunk
    const int crow = tid >> 2;
    const int ccol = (tid & 3) * 16;
    const float* srow = S + (size_t)crow * SK + ccol;
    const int cb = 2 * ccol;                 // byte col base within 128B row
    const uint32_t cswz = (uint32_t)((crow & 7) << 4);
    float m_run = -CUDART_INF_F;
    float zacc = 0.f;

    // MMA maps: warps 2m x 4n over m64 x n256 (warp tile m32 x n64)
    const int wm0 = (wid & 1) * 32;
    const int wn0 = (wid >> 1) * 64;
    const uint32_t xr = (uint32_t)((lane & 7) << 4);
    const uint32_t aRow = (uint32_t)((wm0 + (lane & 15)) * 128);
    const uint32_t aK0  = (uint32_t)(((lane >> 4) & 1) * 16);
    const uint32_t bRow = (uint32_t)((wn0 + (((lane >> 3) & 2) << 2) + (lane & 7)) * 128);
    const uint32_t bK0  = (uint32_t)(((lane >> 3) & 1) * 16);
    const int arow0 = wm0 + (lane >> 2);

    float acc[2][8][4];
#pragma unroll
    for (int i = 0; i < 2; i++)
#pragma unroll
        for (int j = 0; j < 8; j++)
#pragma unroll
            for (int e = 0; e < 4; e++) acc[i][j][e] = 0.f;

    load_V(0, 0);

    for (int t = 0; t < T; t++) {
        const int pb = t & 1;

        // ---- convert S chunk t -> P[pb], fFac[pb] (before the bar) ----
        {
            const float* sp = srow + (size_t)t * 64;
            float v[16];
            float4 v0 = *(const float4*)(sp + 0);
            float4 v1 = *(const float4*)(sp + 4);
            float4 v2 = *(const float4*)(sp + 8);
            float4 v3 = *(const float4*)(sp + 12);
            v[0]=v0.x; v[1]=v0.y; v[2]=v0.z; v[3]=v0.w;
            v[4]=v1.x; v[5]=v1.y; v[6]=v1.z; v[7]=v1.w;
            v[8]=v2.x; v[9]=v2.y; v[10]=v2.z; v[11]=v2.w;
            v[12]=v3.x; v[13]=v3.y; v[14]=v3.z; v[15]=v3.w;
            float lm = v[0];
#pragma unroll
            for (int i = 1; i < 16; i++) lm = fmaxf(lm, v[i]);
            lm = fmaxf(lm, __shfl_xor_sync(0xffffffffu, lm, 1));
            lm = fmaxf(lm, __shfl_xor_sync(0xffffffffu, lm, 2));
            const float m_new = fmaxf(m_run, lm);
            const float fac = __expf(m_run - m_new);   // 0 on first chunk
            m_run = m_new;
            if ((tid & 3) == 0) fFac[pb * 64 + crow] = fac;
            float zc = 0.f;
            uint32_t pk[8];
#pragma unroll
            for (int j = 0; j < 8; j++) {
                float a = __expf(v[2*j]   - m_new);
                float b = __expf(v[2*j+1] - m_new);
                zc += a + b;
                __half2 h = __floats2half2_rn(a, b);
                pk[j] = *(uint32_t*)&h;
            }
            zacc = zacc * fac + zc;
            char* pd = smem + 2 * FC_VST + pb * FC_PST + crow * 128;
            *(uint4*)(pd + ((uint32_t)cb        ^ cswz)) =
                make_uint4(pk[0], pk[1], pk[2], pk[3]);
            *(uint4*)(pd + ((uint32_t)(cb + 16) ^ cswz)) =
                make_uint4(pk[4], pk[5], pk[6], pk[7]);
        }

        CP_WAIT0();        // V(t) landed (the only group in flight)
        __syncthreads();   // publish P(t)/fFac(t)/V(t); compute(t-1) done

        if (t + 1 < T) load_V(t + 1, pb ^ 1);  // overwrites V(t-1) buf: safe

        // ---- rescale acc by fFac[pb], then MMA P[pb] x V[pb] ----
        {
            float f[2][2];
#pragma unroll
            for (int mt = 0; mt < 2; mt++) {
                f[mt][0] = fFac[pb * 64 + arow0 + mt * 16];
                f[mt][1] = fFac[pb * 64 + arow0 + mt * 16 + 8];
            }
#pragma unroll
            for (int mt = 0; mt < 2; mt++)
#pragma unroll
                for (int nt = 0; nt < 8; nt++) {
                    acc[mt][nt][0] *= f[mt][0];
                    acc[mt][nt][1] *= f[mt][0];
                    acc[mt][nt][2] *= f[mt][1];
                    acc[mt][nt][3] *= f[mt][1];
                }

            const uint32_t smPa = smP + pb * FC_PST;
            const uint32_t smVb = smV + pb * FC_VST;
#pragma unroll
            for (int ks = 0; ks < 4; ks++) {
                uint32_t a[2][4], b[4][4];
#pragma unroll
                for (int mt = 0; mt < 2; mt++) {
                    const uint32_t ad = smPa + aRow + mt * 2048 + ((aK0 + ks * 32) ^ xr);
                    LDMATRIX_X4(a[mt][0], a[mt][1], a[mt][2], a[mt][3], ad);
                }
#pragma unroll
                for (int np = 0; np < 4; np++) {
                    const uint32_t bd = smVb + bRow + np * 2048 + ((bK0 + ks * 32) ^ xr);
                    LDMATRIX_X4(b[np][0], b[np][1], b[np][2], b[np][3], bd);
                }
#pragma unroll
                for (int mt = 0; mt < 2; mt++)
#pragma unroll
                    for (int nt = 0; nt < 8; nt++)
                        MMA_F16(acc[mt][nt], a[mt],
                                b[nt >> 1][(nt & 1) * 2], b[nt >> 1][(nt & 1) * 2 + 1]);
            }
        }
    }

    // ---- finalize Z per row, write normalized output ----
    {
        float zq = zacc;
        zq += __shfl_xor_sync(0xffffffffu, zq, 1);
        zq += __shfl_xor_sync(0xffffffffu, zq, 2);
        if ((tid & 3) == 0) fZ[crow] = zq;
    }
    __syncthreads();

    const int bn = wn0 + (lane & 3) * 2;
#pragma unroll
    for (int mt = 0; mt < 2; mt++) {
        const int r0 = arow0 + mt * 16;
        const float iz0 = 1.0f / fZ[r0];
        const float iz1 = 1.0f / fZ[r0 + 8];
#pragma unroll
        for (int nt = 0; nt < 8; nt++) {
            const int n = bn + nt * 8;
            *(float2*)(out + (size_t)r0 * DIM + n) =
                make_float2(acc[mt][nt][0] * iz0, acc[mt][nt][1] * iz0);
            *(float2*)(out + (size_t)(r0 + 8) * DIM + n) =
                make_float2(acc[mt][nt][2] * iz1, acc[mt][nt][3] * iz1);
        }
    }
}

// ---------------- fused-weight prep: Weff = Wa @ Wk (bf16-split out) ------
__global__ void weff_kernel(const float* __restrict__ Wa,
                            const float* __restrict__ Wk,
                            const float* __restrict__ bk,
                            const float* __restrict__ ba,
                            __nv_bfloat16* __restrict__ Weh,
                            __nv_bfloat16* __restrict__ Wel,
                            float* __restrict__ beff) {
    const int e = blockIdx.x;
    const int t = threadIdx.x;
    __shared__ float wa[DIM];
    wa[t] = Wa[e * DIM + t];
    __syncthreads();
    float acc = 0.f;
#pragma unroll 8
    for (int j = 0; j < DIM; j++)
        acc = fmaf(wa[j], Wk[j * DIM + t], acc);
    __nv_bfloat16 hi = __float2bfloat16(acc);
    Weh[e * DIM + t] = hi;
    Wel[e * DIM + t] = __float2bfloat16(acc - __bfloat162float(hi));

    float pb = wa[t] * bk[t];
#pragma unroll
    for (int o = 16; o; o >>= 1)
        pb += __shfl_xor_sync(0xffffffffu, pb, o);
    __shared__ float red[8];
    if ((t & 31) == 0) red[t >> 5] = pb;
    __syncthreads();
    if (t == 0) {
        float s = 0.f;
#pragma unroll
        for (int i = 0; i < 8; i++) s += red[i];
        beff[e] = s + ba[e];
    }
}

// ---------------- merged fp32 -> (hi,lo) bf16 split for 4 tensors ----------
#define NB_ACT (MQ * DIM / 4 / 256)
#define NB_W   (DIM * DIM / 4 / 256)
__global__ void split4_kernel(const float* __restrict__ x,   __nv_bfloat16* xh, __nv_bfloat16* xl,
                              const float* __restrict__ st,  __nv_bfloat16* sh, __nv_bfloat16* sl,
                              const float* __restrict__ wq,  __nv_bfloat16* qh, __nv_bfloat16* ql,
                              const float* __restrict__ wv,  __nv_bfloat16* vh, __nv_bfloat16* vl) {
    int b = blockIdx.x;
    const float* in; __nv_bfloat16 *h, *l;
    if (b < NB_ACT)                   { in = x;  h = xh; l = xl; }
    else if ((b -= NB_ACT) < NB_ACT)  { in = st; h = sh; l = sl; }
    else if ((b -= NB_ACT) < NB_W)    { in = wq; h = qh; l = ql; }
    else { b -= NB_W;                   in = wv; h = vh; l = vl; }
    const size_t i = (size_t)b * 256 + threadIdx.x;
    float4 v = *(const float4*)(in + 4 * i);
    uint32_t h0, l0, h1, l1;
    splitpair_bf(v.x, v.y, h0, l0);
    splitpair_bf(v.z, v.w, h1, l1);
    *(uint2*)(h + 4 * i) = make_uint2(h0, h1);
    *(uint2*)(l + 4 * i) = make_uint2(l0, l1);
}

// ---------------- launcher ----------------
extern "C" void kernel_launch(void* const* d_in, const int* in_sizes, int n_in,
                              void* d_out, int out_size) {
    const float* x      = (const float*)d_in[0];
    const float* states = (const float*)d_in[1];
    const float* Wq = (const float*)d_in[2];
    const float* bq = (const float*)d_in[3];
    const float* Wk = (const float*)d_in[4];
    const float* bk = (const float*)d_in[5];
    const float* Wv = (const float*)d_in[6];
    const float* bv = (const float*)d_in[7];
    const float* Wa = (const float*)d_in[8];
    const float* ba = (const float*)d_in[9];
    float* out = (float*)d_out;

    float *sc, *beff;
    __nv_bfloat16 *xh, *xl, *sh, *sl, *Wqh, *Wql, *Weh, *Wel, *Wvh, *Wvl;
    __nv_bfloat16 *qh, *ql, *wkh, *wkl;
    __half *vT;
    cudaGetSymbolAddress((void**)&sc,   g_scores);
    cudaGetSymbolAddress((void**)&beff, g_beff);
    cudaGetSymbolAddress((void**)&xh,  g_xh);   cudaGetSymbolAddress((void**)&xl,  g_xl);
    cudaGetSymbolAddress((void**)&sh,  g_sh);   cudaGetSymbolAddress((void**)&sl,  g_sl);
    cudaGetSymbolAddress((void**)&Wqh, g_Wqh);  cudaGetSymbolAddress((void**)&Wql, g_Wql);
    cudaGetSymbolAddress((void**)&Weh, g_Weh);  cudaGetSymbolAddress((void**)&Wel, g_Wel);
    cudaGetSymbolAddress((void**)&Wvh, g_Wvh);  cudaGetSymbolAddress((void**)&Wvl, g_Wvl);
    cudaGetSymbolAddress((void**)&qh,  g_qh);   cudaGetSymbolAddress((void**)&ql,  g_ql);
    cudaGetSymbolAddress((void**)&wkh, g_wkh);  cudaGetSymbolAddress((void**)&wkl, g_wkl);
    cudaGetSymbolAddress((void**)&vT,  g_vT);

    cudaFuncSetAttribute(linears_kernel,   cudaFuncAttributeMaxDynamicSharedMemorySize, SMEM_BYTES);
    cudaFuncSetAttribute(scores_kernel,    cudaFuncAttributeMaxDynamicSharedMemorySize, SMEM_BYTES);
    cudaFuncSetAttribute(flash_ctx_kernel, cudaFuncAttributeMaxDynamicSharedMemorySize, FC_SMEM);

    // 1) fold Wa into the K projection (fp32 -> split bf16 directly)
    weff_kernel<<<DIM, DIM>>>(Wa, Wk, bk, ba, Weh, Wel, beff);

    // 2) bf16 splits of x, states, Wq, Wv
    split4_kernel<<<2 * NB_ACT + 2 * NB_W, 256>>>(
        x, xh, xl, states, sh, sl, Wq, Wqh, Wql, Wv, Wvh, Wvl);

    // 3) all three linears in ONE launch (768 CTAs); vT emitted as single fp16
    linears_kernel<<<768, 256, SMEM_BYTES>>>(
        xh, xl, sh, sl, Wqh, Wql, Weh, Wel, Wvh, Wvl,
        qh, ql, wkh, wkl, vT, bq, beff, bv);

    // 4) scores = q @ wk^T per batch  [2048, 2048] x 8, fp32 out
    scores_kernel<<<dim3(SQ / 128, SK / 128, BATCH), 256, SMEM_BYTES>>>(
        qh, ql, wkh, wkl, sc);

    // 5+6) fused online softmax + context -> fp32 out
    flash_ctx_kernel<<<dim3(SQ / 64, 1, BATCH), 256, FC_SMEM>>>(sc, vT, out);
}